// round 17
// baseline (speedup 1.0000x reference)
#include <cuda_runtime.h>
#include <cuda_bf16.h>
#include <cstdint>
#include <cstring>

typedef unsigned long long ull;

#define Bb 512
#define Ss 1024
#define Ff 64
#define Ll 128
#define Gg 512

// recurrent smem layout (bytes)
#define WB    0                    // W staging: 512 rows x 272B (hi, then overwritten with lo)
#define HBUF  139264               // 2 x (HI 2176 + LO 2176) double-buffered h tiles
#define SMR   (139264 + 2 * 4352)  // 147968

__device__ float g_gx[(size_t)Bb * Ss * Gg];
__device__ float g_hall[(size_t)Bb * Ss * Ll];
__device__ float g_weff[Gg * Ll];
__device__ float g_benc[Gg];
__device__ float g_beff[Gg];
__device__ float g_hn[Bb * Ll];
__device__ float g_cn[Bb * Ll];

__device__ __forceinline__ ull pk(float x, float y) {
    ull r; asm("mov.b64 %0, {%1, %2};" : "=l"(r) : "f"(x), "f"(y)); return r;
}
__device__ __forceinline__ void upk(ull v, float& x, float& y) {
    asm("mov.b64 {%0, %1}, %2;" : "=f"(x), "=f"(y) : "l"(v));
}
__device__ __forceinline__ void fma2(ull& d, ull a, ull b) {
    asm("fma.rn.f32x2 %0, %1, %2, %0;" : "+l"(d) : "l"(a), "l"(b));
}
__device__ __forceinline__ float ex2a(float x) {
    float r; asm("ex2.approx.f32 %0, %1;" : "=f"(r) : "f"(x)); return r;
}
__device__ __forceinline__ float rcpa(float x) {
    float r; asm("rcp.approx.f32 %0, %1;" : "=f"(r) : "f"(x)); return r;
}
__device__ __forceinline__ float fsig(float x) {
    return rcpa(1.0f + ex2a(-1.4426950408889634f * x));
}
__device__ __forceinline__ float ftanh(float x) {
    return fmaf(2.0f, rcpa(1.0f + ex2a(-2.8853900817779268f * x)), -1.0f);
}
__device__ __forceinline__ uint32_t smem_u32(const void* p) {
    uint32_t a;
    asm("{ .reg .u64 t; cvta.to.shared.u64 t, %1; cvt.u32.u64 %0, t; }" : "=r"(a) : "l"(p));
    return a;
}
__device__ __forceinline__ void ldsm4(uint32_t* f, uint32_t a) {
    asm volatile("ldmatrix.sync.aligned.m8n8.x4.shared.b16 {%0,%1,%2,%3}, [%4];"
                 : "=r"(f[0]), "=r"(f[1]), "=r"(f[2]), "=r"(f[3]) : "r"(a));
}
__device__ __forceinline__ void ldsm2(uint32_t* f, uint32_t a) {
    asm volatile("ldmatrix.sync.aligned.m8n8.x2.shared.b16 {%0,%1}, [%2];"
                 : "=r"(f[0]), "=r"(f[1]) : "r"(a));
}
__device__ __forceinline__ void mma_bf16(float* d, const uint32_t* a, const uint32_t* b) {
    asm volatile("mma.sync.aligned.m16n8k16.row.col.f32.bf16.bf16.f32 "
                 "{%0,%1,%2,%3},{%4,%5,%6,%7},{%8,%9},{%0,%1,%2,%3};"
                 : "+f"(d[0]), "+f"(d[1]), "+f"(d[2]), "+f"(d[3])
                 : "r"(a[0]), "r"(a[1]), "r"(a[2]), "r"(a[3]), "r"(b[0]), "r"(b[1]));
}
__device__ __forceinline__ uint16_t bf16u(float v) {
    __nv_bfloat16 b = __float2bfloat16(v);
    uint16_t u; memcpy(&u, &b, 2); return u;
}
__device__ __forceinline__ float bf16f(uint16_t u) {
    __nv_bfloat16 b; memcpy(&b, &u, 2);
    return __bfloat162float(b);
}

// ------------------------- setup -------------------------
__global__ void setup_kernel(const float* __restrict__ Wih_d, const float* __restrict__ Whh_d,
                             const float* __restrict__ bih_d, const float* __restrict__ bhh_d,
                             const float* __restrict__ Wdn, const float* __restrict__ bdn,
                             const float* __restrict__ bih_e, const float* __restrict__ bhh_e) {
    int j = blockIdx.x, k = threadIdx.x;
    float s = 0.0f;
    for (int m = 0; m < Ff; m++) s += Wih_d[j * Ff + m] * Wdn[m * Ll + k];
    g_weff[j * Ll + k] = Whh_d[j * Ll + k] + s;
    if (k == 0) {
        float bs = bih_d[j] + bhh_d[j];
        for (int m = 0; m < Ff; m++) bs += Wih_d[j * Ff + m] * bdn[m];
        g_beff[j] = bs;
        g_benc[j] = bih_e[j] + bhh_e[j];
    }
}

// ------------------------- x-projection (fp32 scalar, proven) -------------------------
__global__ void __launch_bounds__(256, 1)
xproj_kernel(const float* __restrict__ x, const float* __restrict__ Wih) {
    extern __shared__ char smraw[];
    ulonglong2* Wsm = (ulonglong2*)smraw;
    float* xs = (float*)(smraw + 16 * 512 * 16);
    const int t_ = threadIdx.x;
    const int gA = t_, gB = t_ + 256;
    const float4* wa = (const float4*)(Wih + gA * Ff);
    const float4* wb = (const float4*)(Wih + gB * Ff);
#pragma unroll
    for (int kg = 0; kg < 16; kg++) {
        ((float4*)Wsm)[kg * 512 + gA] = wa[kg];
        ((float4*)Wsm)[kg * 512 + gB] = wb[kg];
    }
    const float bA = g_benc[gA], bB = g_benc[gB];
    const size_t row0 = (size_t)blockIdx.x * 32;
    ((float4*)xs)[t_] = ((const float4*)x)[row0 * 16 + t_];
    ((float4*)xs)[t_ + 256] = ((const float4*)x)[row0 * 16 + t_ + 256];
    __syncthreads();
    ull aA[32], aB[32];
#pragma unroll
    for (int r = 0; r < 32; r++) { aA[r] = 0ull; aB[r] = 0ull; }
#pragma unroll 4
    for (int kg = 0; kg < 16; kg++) {
        ulonglong2 wAv = Wsm[kg * 512 + gA];
        ulonglong2 wBv = Wsm[kg * 512 + gB];
#pragma unroll
        for (int r = 0; r < 32; r++) {
            ulonglong2 hh = *(const ulonglong2*)(xs + r * Ff + 4 * kg);
            fma2(aA[r], hh.x, wAv.x); fma2(aA[r], hh.y, wAv.y);
            fma2(aB[r], hh.x, wBv.x); fma2(aB[r], hh.y, wBv.y);
        }
    }
#pragma unroll
    for (int r = 0; r < 32; r++) {
        float lo, hi;
        upk(aA[r], lo, hi); g_gx[(row0 + r) * Gg + gA] = lo + hi + bA;
        upk(aB[r], lo, hi); g_gx[(row0 + r) * Gg + gB] = lo + hi + bB;
    }
}

// ------------------------- recurrent: mma.sync, fragment-local cell update -------------------------
// 128 CTAs x 512 threads; 4 real batch rows (B cols 0-3; cols 4-7 zero padding).
// W rows PERMUTED: warp w, mt0 tile rows = [i0..i7, f0..f7], mt1 rows = [g0..g7, o0..o7]
// of latents 8w..8w+7. Thread (q=lane>>2, cc=lane&3) holds all 4 gates of latent
// L=8w+q for batch rows 2cc, 2cc+1 in its D fragments -> thread-local cell update.
// h double-buffered bf16 hi/lo tiles; ONE barrier per step.
// D = Whi*hhi + Wlo*hhi + Whi*hlo (3 independent accumulator chains).
template <bool ENC>
__global__ void __launch_bounds__(512, 1)
rec_kernel(const float* __restrict__ Wsrc) {
    extern __shared__ char sm[];
    const uint32_t smb = smem_u32(sm);
    const int tid = threadIdx.x;
    const int lane = tid & 31, w = tid >> 5;
    const int q = lane >> 2, cc = lane & 3;
    const int L = w * 8 + q;
    const int r0 = 2 * cc, r1 = 2 * cc + 1;
    const bool act = (cc < 2);
    const int b0 = blockIdx.x * 4;
    const float* W = ENC ? Wsrc : (const float*)g_weff;

    // stage W_hi (permuted rows): drow = mg*16+rr, mg = w*2+mt;
    // gate row = (mt*2 + (rr>>3))*128 + w*8 + (rr&7)
    for (int idx = tid; idx < 512 * 128; idx += 512) {
        int drow = idx >> 7, k = idx & 127;
        int mg = drow >> 4, rr = drow & 15;
        int g = (((mg & 1) * 2 + (rr >> 3)) << 7) + ((mg >> 1) << 3) + (rr & 7);
        *(__nv_bfloat16*)(sm + WB + drow * 272 + 2 * k) = __float2bfloat16(W[g * 128 + k]);
    }
    __syncthreads();

    const uint32_t laneA = (uint32_t)((lane & 15) * 272 + (lane >> 4) * 16);
    const uint32_t laneB = (uint32_t)((lane & 7) * 272 + ((lane >> 3) & 1) * 16);

    uint32_t Ahi[2][8][4];
#pragma unroll
    for (int mt = 0; mt < 2; mt++) {
        uint32_t gb = smb + WB + (uint32_t)((w * 2 + mt) * 16) * 272 + laneA;
#pragma unroll
        for (int kt = 0; kt < 8; kt++) ldsm4(Ahi[mt][kt], gb + kt * 32);
    }
    __syncthreads();

    // overwrite WB with W_lo residuals (same permuted order)
    for (int idx = tid; idx < 512 * 128; idx += 512) {
        int drow = idx >> 7, k = idx & 127;
        int mg = drow >> 4, rr = drow & 15;
        int g = (((mg & 1) * 2 + (rr >> 3)) << 7) + ((mg >> 1) << 3) + (rr & 7);
        float wv = W[g * 128 + k];
        __nv_bfloat16 hh = __float2bfloat16(wv);
        *(__nv_bfloat16*)(sm + WB + drow * 272 + 2 * k) =
            __float2bfloat16(wv - __bfloat162float(hh));
    }
    // zero both h double-buffers (2 x 4352B = 2176 words)
    for (int idx = tid; idx < 2176; idx += 512) ((uint32_t*)(sm + HBUF))[idx] = 0u;

    float c0 = 0.0f, c1 = 0.0f, be0 = 0.0f, be1 = 0.0f, be2 = 0.0f, be3 = 0.0f;
    if (!ENC) {
        if (act) {
            c0 = g_cn[(b0 + r0) * Ll + L];
            c1 = g_cn[(b0 + r1) * Ll + L];
        }
        be0 = g_beff[L]; be1 = g_beff[128 + L]; be2 = g_beff[256 + L]; be3 = g_beff[384 + L];
    }
    __syncthreads();
    if (!ENC) {  // seed h (buffer 0) from encoder state
        if (act) {
            float h0 = g_hn[(b0 + r0) * Ll + L];
            float h1 = g_hn[(b0 + r1) * Ll + L];
            uint16_t h0h = bf16u(h0), h1h = bf16u(h1);
            *(uint16_t*)(sm + HBUF + r0 * 272 + 2 * L) = h0h;
            *(uint16_t*)(sm + HBUF + r1 * 272 + 2 * L) = h1h;
            *(uint16_t*)(sm + HBUF + 2176 + r0 * 272 + 2 * L) = bf16u(h0 - bf16f(h0h));
            *(uint16_t*)(sm + HBUF + 2176 + r1 * 272 + 2 * L) = bf16u(h1 - bf16f(h1h));
        }
        __syncthreads();
    }

    float hn0 = 0.0f, hn1 = 0.0f;
    int p = 0;
    for (int t = 0; t < Ss; t++) {
        float gxi0, gxi1, gxf0, gxf1, gxg0, gxg1, gxo0, gxo1;
        if (ENC && act) {
            const float* p0 = g_gx + ((size_t)(b0 + r0) * Ss + t) * Gg;
            const float* p1 = g_gx + ((size_t)(b0 + r1) * Ss + t) * Gg;
            gxi0 = p0[L];       gxi1 = p1[L];
            gxf0 = p0[128 + L]; gxf1 = p1[128 + L];
            gxg0 = p0[256 + L]; gxg1 = p1[256 + L];
            gxo0 = p0[384 + L]; gxo1 = p1[384 + L];
        }
        const uint32_t bHI = smb + HBUF + p * 4352;
        const uint32_t bLO = bHI + 2176;
        uint32_t Bh[8][2];
#pragma unroll
        for (int kt = 0; kt < 8; kt++) ldsm2(Bh[kt], bHI + laneB + kt * 32);

        float res[2][4];
#pragma unroll
        for (int mt = 0; mt < 2; mt++) {
            float DA[4] = {0.f, 0.f, 0.f, 0.f};
            float DB[4] = {0.f, 0.f, 0.f, 0.f};
            float DC[4] = {0.f, 0.f, 0.f, 0.f};
            uint32_t gb = smb + WB + (uint32_t)((w * 2 + mt) * 16) * 272 + laneA;
#pragma unroll
            for (int kt = 0; kt < 8; kt++) {
                uint32_t Al[4], Bl[2];
                ldsm4(Al, gb + kt * 32);
                ldsm2(Bl, bLO + laneB + kt * 32);
                mma_bf16(DA, Ahi[mt][kt], Bh[kt]);   // hi*hi
                mma_bf16(DB, Al,          Bh[kt]);   // lo*hi
                mma_bf16(DC, Ahi[mt][kt], Bl);       // hi*lo
            }
#pragma unroll
            for (int e = 0; e < 4; e++) res[mt][e] = DA[e] + DB[e] + DC[e];
        }
        // fragment-local cell update: mt0 = {i: d0,d1 | f: d2,d3}, mt1 = {g | o}
        if (act) {
            float vi0 = res[0][0] + (ENC ? gxi0 : be0);
            float vi1 = res[0][1] + (ENC ? gxi1 : be0);
            float vf0 = res[0][2] + (ENC ? gxf0 : be1);
            float vf1 = res[0][3] + (ENC ? gxf1 : be1);
            float vg0 = res[1][0] + (ENC ? gxg0 : be2);
            float vg1 = res[1][1] + (ENC ? gxg1 : be2);
            float vo0 = res[1][2] + (ENC ? gxo0 : be3);
            float vo1 = res[1][3] + (ENC ? gxo1 : be3);
            c0 = fsig(vf0) * c0 + fsig(vi0) * ftanh(vg0);
            c1 = fsig(vf1) * c1 + fsig(vi1) * ftanh(vg1);
            hn0 = fsig(vo0) * ftanh(c0);
            hn1 = fsig(vo1) * ftanh(c1);
            char* nb = sm + HBUF + (p ^ 1) * 4352;
            uint16_t h0h = bf16u(hn0), h1h = bf16u(hn1);
            *(uint16_t*)(nb + r0 * 272 + 2 * L) = h0h;
            *(uint16_t*)(nb + r1 * 272 + 2 * L) = h1h;
            *(uint16_t*)(nb + 2176 + r0 * 272 + 2 * L) = bf16u(hn0 - bf16f(h0h));
            *(uint16_t*)(nb + 2176 + r1 * 272 + 2 * L) = bf16u(hn1 - bf16f(h1h));
            if (!ENC) {
                g_hall[((size_t)(b0 + r0) * Ss + t) * Ll + L] = hn0;
                g_hall[((size_t)(b0 + r1) * Ss + t) * Ll + L] = hn1;
            }
        }
        p ^= 1;
        __syncthreads();
    }
    if (ENC && act) {
        g_hn[(b0 + r0) * Ll + L] = hn0;
        g_hn[(b0 + r1) * Ll + L] = hn1;
        g_cn[(b0 + r0) * Ll + L] = c0;
        g_cn[(b0 + r1) * Ll + L] = c1;
    }
}

// ------------------------- output GEMM + flip (proven) -------------------------
__global__ void __launch_bounds__(256, 1)
out_kernel(const float* __restrict__ Wdn, const float* __restrict__ bdn,
           float* __restrict__ out) {
    extern __shared__ float hsm[];
    const int tid = threadIdx.x;
    const size_t row0 = (size_t)blockIdx.x * 128;
    for (int i = tid; i < 128 * Ll / 4; i += 256)
        ((float4*)hsm)[i] = ((const float4*)g_hall)[row0 * (Ll / 4) + i];
    const int f = tid & 63, rgq = tid >> 6;
    ull Wd[64];
    const float4* wd = (const float4*)(Wdn + f * Ll);
#pragma unroll
    for (int q = 0; q < 32; q++) {
        float4 v = wd[q];
        Wd[2 * q] = pk(v.x, v.y); Wd[2 * q + 1] = pk(v.z, v.w);
    }
    const float bv = bdn[f];
    __syncthreads();
#pragma unroll 1
    for (int rr = 0; rr < 32; rr += 2) {
        int row = rgq * 32 + rr;
        ull a0 = 0, a1 = 0;
#pragma unroll
        for (int q = 0; q < 32; q++) {
            ulonglong2 h0 = *(const ulonglong2*)(hsm + row * Ll + 4 * q);
            ulonglong2 h1 = *(const ulonglong2*)(hsm + (row + 1) * Ll + 4 * q);
            fma2(a0, h0.x, Wd[2 * q]); fma2(a0, h0.y, Wd[2 * q + 1]);
            fma2(a1, h1.x, Wd[2 * q]); fma2(a1, h1.y, Wd[2 * q + 1]);
        }
        float lo, hi;
        upk(a0, lo, hi); float s0 = lo + hi + bv;
        upk(a1, lo, hi); float s1 = lo + hi + bv;
        size_t g0 = row0 + row;
        size_t b_ = g0 >> 10; int t_ = (int)(g0 & 1023);
        out[(b_ * Ss + (size_t)(Ss - 1 - t_)) * Ff + f] = s0;
        g0 += 1; b_ = g0 >> 10; t_ = (int)(g0 & 1023);
        out[(b_ * Ss + (size_t)(Ss - 1 - t_)) * Ff + f] = s1;
    }
}

// ------------------------- launch -------------------------
extern "C" void kernel_launch(void* const* d_in, const int* in_sizes, int n_in,
                              void* d_out, int out_size) {
    const float* x     = (const float*)d_in[0];
    const float* Wih_e = (const float*)d_in[1];
    const float* Whh_e = (const float*)d_in[2];
    const float* bih_e = (const float*)d_in[3];
    const float* bhh_e = (const float*)d_in[4];
    const float* Wih_d = (const float*)d_in[5];
    const float* Whh_d = (const float*)d_in[6];
    const float* bih_d = (const float*)d_in[7];
    const float* bhh_d = (const float*)d_in[8];
    const float* Wdn   = (const float*)d_in[9];
    const float* bdn   = (const float*)d_in[10];
    float* out = (float*)d_out;

    const int SM_X = 16 * 512 * 16 + 32 * 64 * 4;
    const int SM_O = 128 * Ll * 4;

    cudaFuncSetAttribute(xproj_kernel, cudaFuncAttributeMaxDynamicSharedMemorySize, SM_X);
    cudaFuncSetAttribute(rec_kernel<true>,  cudaFuncAttributeMaxDynamicSharedMemorySize, SMR);
    cudaFuncSetAttribute(rec_kernel<false>, cudaFuncAttributeMaxDynamicSharedMemorySize, SMR);
    cudaFuncSetAttribute(out_kernel, cudaFuncAttributeMaxDynamicSharedMemorySize, SM_O);

    setup_kernel<<<Gg, Ll>>>(Wih_d, Whh_d, bih_d, bhh_d, Wdn, bdn, bih_e, bhh_e);
    xproj_kernel<<<(Bb * Ss) / 32, 256, SM_X>>>(x, Wih_e);
    rec_kernel<true><<<Bb / 4, 512, SMR>>>(Whh_e);
    rec_kernel<false><<<Bb / 4, 512, SMR>>>(Whh_e);
    out_kernel<<<(Bb * Ss) / 128, 256, SM_O>>>(Wdn, bdn, out);
}